// round 5
// baseline (speedup 1.0000x reference)
#include <cuda_runtime.h>

#define N_NODES  100000
#define N_EDGES  3200000
#define N_GRAPHS 128

// ---------------- scratch (device globals; no allocation allowed) ------------
__device__ float g_dinv[N_NODES];              // deg, then rsqrt(deg) in place
__device__ int   g_src[N_EDGES];
__device__ int   g_dst[N_EDGES];
__device__ float g_norm[N_EDGES];
__device__ float g_t1[N_NODES * 3];            // aggregated x (3-wide)
__device__ __align__(16) float g_h1[N_NODES * 32];  // relu(t1@W1+b1)
__device__ __align__(16) float g_t2[N_NODES * 32];  // aggregated h1 (32-wide)
__device__ __align__(8)  float g_p [N_NODES * 2];   // (relu(t2@W2+b2))@W3
__device__ __align__(8)  float g_t3[N_NODES * 2];   // aggregated p (2-wide)
__device__ float g_gsum[N_GRAPHS * 2];
__device__ float g_gcnt[N_GRAPHS];

// ---------------- kernels ----------------------------------------------------

// K1: deg starts at 1 (self-loop); zero pooling accumulators
__global__ void k_init() {
    int i = blockIdx.x * blockDim.x + threadIdx.x;
    if (i < N_NODES)      g_dinv[i] = 1.0f;
    if (i < N_GRAPHS * 2) g_gsum[i] = 0.0f;
    if (i < N_GRAPHS)     g_gcnt[i] = 0.0f;
}

// K2: copy int32 indices into scratch, count in-degree
__global__ void k_deg(const int* __restrict__ ei) {
    int e = blockIdx.x * blockDim.x + threadIdx.x;
    if (e >= N_EDGES) return;
    int s = ei[e];
    int d = ei[N_EDGES + e];
    g_src[e] = s;
    g_dst[e] = d;
    atomicAdd(&g_dinv[d], 1.0f);
}

// K3: dinv = rsqrt(deg); init t1 with self-loop term dinv^2 * x
__global__ void k_dinv_t1(const float* __restrict__ x) {
    int i = blockIdx.x * blockDim.x + threadIdx.x;
    if (i >= N_NODES) return;
    float dv = rsqrtf(g_dinv[i]);
    g_dinv[i] = dv;
    float s = dv * dv;
    g_t1[3 * i + 0] = s * x[3 * i + 0];
    g_t1[3 * i + 1] = s * x[3 * i + 1];
    g_t1[3 * i + 2] = s * x[3 * i + 2];
}

// K4: per-edge norm (cached for L2/L3) + layer-1 aggregation at width 3
__global__ void k_edge_l1(const float* __restrict__ x) {
    int e = blockIdx.x * blockDim.x + threadIdx.x;
    if (e >= N_EDGES) return;
    int s = g_src[e], d = g_dst[e];
    float nv = g_dinv[s] * g_dinv[d];
    g_norm[e] = nv;
    atomicAdd(&g_t1[3 * d + 0], nv * x[3 * s + 0]);
    atomicAdd(&g_t1[3 * d + 1], nv * x[3 * s + 1]);
    atomicAdd(&g_t1[3 * d + 2], nv * x[3 * s + 2]);
}

// K5: h1 = relu(t1 @ W1 + b1); init t2 with self-loop term. One warp per node.
__global__ void k_node_l1(const float* __restrict__ W1, const float* __restrict__ b1) {
    int gid = blockIdx.x * blockDim.x + threadIdx.x;
    int n = gid >> 5;
    int f = gid & 31;
    if (n >= N_NODES) return;
    float t0 = g_t1[3 * n + 0];
    float t1 = g_t1[3 * n + 1];
    float t2 = g_t1[3 * n + 2];
    float acc = b1[f];
    acc = fmaf(t0, W1[f], acc);
    acc = fmaf(t1, W1[32 + f], acc);
    acc = fmaf(t2, W1[64 + f], acc);
    acc = fmaxf(acc, 0.0f);
    g_h1[32 * n + f] = acc;
    float dv = g_dinv[n];
    g_t2[32 * n + f] = dv * dv * acc;
}

// K6: layer-2 edge aggregation at width 32: 8 threads/edge, float4 + red.v4
__global__ void k_edge_l2() {
    int gid = blockIdx.x * blockDim.x + threadIdx.x;
    int e = gid >> 3;
    if (e >= N_EDGES) return;
    int q = (gid & 7) << 2;
    int s = g_src[e], d = g_dst[e];
    float nv = g_norm[e];
    const float4 v = *reinterpret_cast<const float4*>(&g_h1[32 * s + q]);
    float* dst = &g_t2[32 * d + q];
    asm volatile("red.global.add.v4.f32 [%0], {%1,%2,%3,%4};"
                 :: "l"(dst), "f"(nv * v.x), "f"(nv * v.y), "f"(nv * v.z), "f"(nv * v.w)
                 : "memory");
}

// K7: fused node math: h2 = relu(t2@W2 + b2); p = h2@W3; init t3 self-loop term.
// One warp per node; lane f owns hidden channels f and f+32.
__global__ void k_node_l23(const float* __restrict__ W2, const float* __restrict__ b2,
                           const float* __restrict__ W3) {
    __shared__ float sW2[32 * 64];
    __shared__ float sW3[64 * 2];
    __shared__ float sb2[64];
    int tid = threadIdx.x;
    for (int i = tid; i < 32 * 64; i += blockDim.x) sW2[i] = W2[i];
    if (tid < 128) sW3[tid] = W3[tid];
    if (tid < 64)  sb2[tid] = b2[tid];
    __syncthreads();

    int warp = (blockIdx.x * blockDim.x + tid) >> 5;
    int lane = tid & 31;
    if (warp >= N_NODES) return;

    float myt = g_t2[32 * warp + lane];
    float a0 = sb2[lane];
    float a1 = sb2[lane + 32];
#pragma unroll
    for (int k = 0; k < 32; k++) {
        float tk = __shfl_sync(0xffffffffu, myt, k);
        a0 = fmaf(tk, sW2[k * 64 + lane], a0);
        a1 = fmaf(tk, sW2[k * 64 + lane + 32], a1);
    }
    a0 = fmaxf(a0, 0.0f);
    a1 = fmaxf(a1, 0.0f);
    float c0 = a0 * sW3[lane * 2 + 0] + a1 * sW3[(lane + 32) * 2 + 0];
    float c1 = a0 * sW3[lane * 2 + 1] + a1 * sW3[(lane + 32) * 2 + 1];
#pragma unroll
    for (int off = 16; off > 0; off >>= 1) {
        c0 += __shfl_down_sync(0xffffffffu, c0, off);
        c1 += __shfl_down_sync(0xffffffffu, c1, off);
    }
    if (lane == 0) {
        g_p[2 * warp + 0] = c0;
        g_p[2 * warp + 1] = c1;
        float dv = g_dinv[warp];
        float ss = dv * dv;
        g_t3[2 * warp + 0] = ss * c0;
        g_t3[2 * warp + 1] = ss * c1;
    }
}

// K8: layer-3 edge aggregation at width 2 (red.v2)
__global__ void k_edge_l3() {
    int e = blockIdx.x * blockDim.x + threadIdx.x;
    if (e >= N_EDGES) return;
    int s = g_src[e], d = g_dst[e];
    float nv = g_norm[e];
    float p0 = g_p[2 * s + 0];
    float p1 = g_p[2 * s + 1];
    float* dst = &g_t3[2 * d];
    asm volatile("red.global.add.v2.f32 [%0], {%1,%2};"
                 :: "l"(dst), "f"(nv * p0), "f"(nv * p1)
                 : "memory");
}

// K9: mean-pool phase 1 — shared-memory pre-reduction per block (batch sorted)
__global__ void k_pool(const int* __restrict__ batch) {
    __shared__ float ss[N_GRAPHS * 2];
    __shared__ float sc[N_GRAPHS];
    int tid = threadIdx.x;
    for (int i = tid; i < N_GRAPHS * 2; i += blockDim.x) ss[i] = 0.0f;
    for (int i = tid; i < N_GRAPHS; i += blockDim.x)     sc[i] = 0.0f;
    __syncthreads();
    int n = blockIdx.x * blockDim.x + tid;
    if (n < N_NODES) {
        int g = batch[n];
        atomicAdd(&ss[2 * g + 0], g_t3[2 * n + 0]);
        atomicAdd(&ss[2 * g + 1], g_t3[2 * n + 1]);
        atomicAdd(&sc[g], 1.0f);
    }
    __syncthreads();
    if (tid < N_GRAPHS * 2) atomicAdd(&g_gsum[tid], ss[tid]);
    if (tid < N_GRAPHS)     atomicAdd(&g_gcnt[tid], sc[tid]);
}

// K10: finalize out = gsum/cnt + b3
__global__ void k_final(const float* __restrict__ b3, float* __restrict__ out) {
    int i = threadIdx.x;
    if (i < N_GRAPHS * 2) {
        int g = i >> 1, j = i & 1;
        out[i] = g_gsum[i] / fmaxf(g_gcnt[g], 1.0f) + b3[j];
    }
}

// ---------------- launch ------------------------------------------------------
extern "C" void kernel_launch(void* const* d_in, const int* in_sizes, int n_in,
                              void* d_out, int out_size) {
    const float* x     = (const float*)d_in[0];
    const int*   ei    = (const int*)d_in[1];    // int32! (JAX x64 disabled)
    const int*   batch = (const int*)d_in[2];    // int32!
    const float* W1    = (const float*)d_in[3];
    const float* b1    = (const float*)d_in[4];
    const float* W2    = (const float*)d_in[5];
    const float* b2    = (const float*)d_in[6];
    const float* W3    = (const float*)d_in[7];
    const float* b3    = (const float*)d_in[8];
    float* out = (float*)d_out;

    const int TB = 256;
    const int nb_nodes = (N_NODES + TB - 1) / TB;            // 391
    const int nb_edges = (N_EDGES + TB - 1) / TB;            // 12500
    const int nb_nwarp = (N_NODES * 32 + TB - 1) / TB;       // 12500
    const int nb_e8    = (N_EDGES * 8 + TB - 1) / TB;        // 100000

    k_init<<<nb_nodes, TB>>>();
    k_deg<<<nb_edges, TB>>>(ei);
    k_dinv_t1<<<nb_nodes, TB>>>(x);
    k_edge_l1<<<nb_edges, TB>>>(x);
    k_node_l1<<<nb_nwarp, TB>>>(W1, b1);
    k_edge_l2<<<nb_e8, TB>>>();
    k_node_l23<<<nb_nwarp, TB>>>(W2, b2, W3);
    k_edge_l3<<<nb_edges, TB>>>();
    k_pool<<<nb_nodes, TB>>>(batch);
    k_final<<<1, 256>>>(b3, out);
}

// round 10
// speedup vs baseline: 1.1637x; 1.1637x over previous
#include <cuda_runtime.h>

#define N_NODES  100000
#define N_EDGES  3200000
#define N_GRAPHS 128

// ---------------- scratch (device globals; no allocation allowed) ------------
__device__ float g_dinv[N_NODES];                    // deg, then rsqrt(deg)
__device__ __align__(16) float g_y  [N_NODES * 4];   // (dinv*x0, dinv*x1, dinv*x2, dinv)
__device__ __align__(16) float g_t1 [N_NODES * 4];   // aggregated, padded to 4
__device__ float g_norm[N_EDGES];
__device__ __align__(16) float g_h1[N_NODES * 32];   // relu(t1@W1+b1)
__device__ __align__(16) float g_t2[N_NODES * 32];   // aggregated h1 (32-wide)
__device__ __align__(8)  float g_p [N_NODES * 2];    // (relu(t2@W2+b2))@W3
__device__ __align__(8)  float g_t3[N_NODES * 2];    // aggregated p (2-wide)
__device__ float g_gsum[N_GRAPHS * 2];
__device__ float g_gcnt[N_GRAPHS];

// ---------------- kernels ----------------------------------------------------

// K1: deg starts at 1 (self-loop); zero pooling accumulators
__global__ void k_init() {
    int i = blockIdx.x * blockDim.x + threadIdx.x;
    if (i < N_NODES)      g_dinv[i] = 1.0f;
    if (i < N_GRAPHS * 2) g_gsum[i] = 0.0f;
    if (i < N_GRAPHS)     g_gcnt[i] = 0.0f;
}

// K2: count in-degree (reads edge_index directly; no copy)
__global__ void k_deg(const int* __restrict__ ei) {
    int e = blockIdx.x * blockDim.x + threadIdx.x;
    if (e >= N_EDGES) return;
    atomicAdd(&g_dinv[ei[N_EDGES + e]], 1.0f);
}

// K3: dinv = rsqrt(deg); build y = (dinv*x, dinv); init t1 self term dinv^2*x
__global__ void k_dinv_t1(const float* __restrict__ x) {
    int i = blockIdx.x * blockDim.x + threadIdx.x;
    if (i >= N_NODES) return;
    float dv = rsqrtf(g_dinv[i]);
    g_dinv[i] = dv;
    float x0 = x[3 * i + 0], x1 = x[3 * i + 1], x2 = x[3 * i + 2];
    float4 y = make_float4(dv * x0, dv * x1, dv * x2, dv);
    *reinterpret_cast<float4*>(&g_y[4 * i]) = y;
    float s = dv * dv;
    *reinterpret_cast<float4*>(&g_t1[4 * i]) = make_float4(s * x0, s * x1, s * x2, s);
}

// K4: layer-1 edge aggregation at width 4 (one gather + one red.v4 per edge)
//     also materializes per-edge norm for layers 2/3
__global__ void k_edge_l1(const int* __restrict__ ei) {
    int e = blockIdx.x * blockDim.x + threadIdx.x;
    if (e >= N_EDGES) return;
    int s = ei[e];
    int d = ei[N_EDGES + e];
    const float4 ys = *reinterpret_cast<const float4*>(&g_y[4 * s]);
    float dd = g_dinv[d];
    float nv = ys.w * dd;          // dinv[s] * dinv[d]
    g_norm[e] = nv;
    float* dst = &g_t1[4 * d];
    asm volatile("red.global.add.v4.f32 [%0], {%1,%2,%3,%4};"
                 :: "l"(dst), "f"(dd * ys.x), "f"(dd * ys.y), "f"(dd * ys.z), "f"(dd * ys.w)
                 : "memory");
}

// K5: h1 = relu(t1 @ W1 + b1); init t2 with self-loop term. One warp per node.
__global__ void k_node_l1(const float* __restrict__ W1, const float* __restrict__ b1) {
    int gid = blockIdx.x * blockDim.x + threadIdx.x;
    int n = gid >> 5;
    int f = gid & 31;
    if (n >= N_NODES) return;
    const float4 t = *reinterpret_cast<const float4*>(&g_t1[4 * n]);  // broadcast
    float acc = b1[f];
    acc = fmaf(t.x, W1[f], acc);
    acc = fmaf(t.y, W1[32 + f], acc);
    acc = fmaf(t.z, W1[64 + f], acc);
    acc = fmaxf(acc, 0.0f);
    g_h1[32 * n + f] = acc;
    float dv = g_dinv[n];
    g_t2[32 * n + f] = dv * dv * acc;
}

// K6: layer-2 edge aggregation at width 32: 8 threads/edge, float4 + red.v4
__global__ void k_edge_l2(const int* __restrict__ ei) {
    int gid = blockIdx.x * blockDim.x + threadIdx.x;
    int e = gid >> 3;
    if (e >= N_EDGES) return;
    int q = (gid & 7) << 2;
    int s = ei[e];
    int d = ei[N_EDGES + e];
    float nv = g_norm[e];
    const float4 v = *reinterpret_cast<const float4*>(&g_h1[32 * s + q]);
    float* dst = &g_t2[32 * d + q];
    asm volatile("red.global.add.v4.f32 [%0], {%1,%2,%3,%4};"
                 :: "l"(dst), "f"(nv * v.x), "f"(nv * v.y), "f"(nv * v.z), "f"(nv * v.w)
                 : "memory");
}

// K7: fused node math: h2 = relu(t2@W2 + b2); p = h2@W3; init t3 self-loop term.
__global__ void k_node_l23(const float* __restrict__ W2, const float* __restrict__ b2,
                           const float* __restrict__ W3) {
    __shared__ float sW2[32 * 64];
    __shared__ float sW3[64 * 2];
    __shared__ float sb2[64];
    int tid = threadIdx.x;
    for (int i = tid; i < 32 * 64; i += blockDim.x) sW2[i] = W2[i];
    if (tid < 128) sW3[tid] = W3[tid];
    if (tid < 64)  sb2[tid] = b2[tid];
    __syncthreads();

    int warp = (blockIdx.x * blockDim.x + tid) >> 5;
    int lane = tid & 31;
    if (warp >= N_NODES) return;

    float myt = g_t2[32 * warp + lane];
    float a0 = sb2[lane];
    float a1 = sb2[lane + 32];
#pragma unroll
    for (int k = 0; k < 32; k++) {
        float tk = __shfl_sync(0xffffffffu, myt, k);
        a0 = fmaf(tk, sW2[k * 64 + lane], a0);
        a1 = fmaf(tk, sW2[k * 64 + lane + 32], a1);
    }
    a0 = fmaxf(a0, 0.0f);
    a1 = fmaxf(a1, 0.0f);
    float c0 = a0 * sW3[lane * 2 + 0] + a1 * sW3[(lane + 32) * 2 + 0];
    float c1 = a0 * sW3[lane * 2 + 1] + a1 * sW3[(lane + 32) * 2 + 1];
#pragma unroll
    for (int off = 16; off > 0; off >>= 1) {
        c0 += __shfl_down_sync(0xffffffffu, c0, off);
        c1 += __shfl_down_sync(0xffffffffu, c1, off);
    }
    if (lane == 0) {
        g_p[2 * warp + 0] = c0;
        g_p[2 * warp + 1] = c1;
        float dv = g_dinv[warp];
        float ss = dv * dv;
        g_t3[2 * warp + 0] = ss * c0;
        g_t3[2 * warp + 1] = ss * c1;
    }
}

// K8: layer-3 edge aggregation at width 2 (red.v2)
__global__ void k_edge_l3(const int* __restrict__ ei) {
    int e = blockIdx.x * blockDim.x + threadIdx.x;
    if (e >= N_EDGES) return;
    int s = ei[e];
    int d = ei[N_EDGES + e];
    float nv = g_norm[e];
    float p0 = g_p[2 * s + 0];
    float p1 = g_p[2 * s + 1];
    float* dst = &g_t3[2 * d];
    asm volatile("red.global.add.v2.f32 [%0], {%1,%2};"
                 :: "l"(dst), "f"(nv * p0), "f"(nv * p1)
                 : "memory");
}

// K9: mean-pool phase 1 — shared-memory pre-reduction per block (batch sorted)
__global__ void k_pool(const int* __restrict__ batch) {
    __shared__ float ss[N_GRAPHS * 2];
    __shared__ float sc[N_GRAPHS];
    int tid = threadIdx.x;
    for (int i = tid; i < N_GRAPHS * 2; i += blockDim.x) ss[i] = 0.0f;
    for (int i = tid; i < N_GRAPHS; i += blockDim.x)     sc[i] = 0.0f;
    __syncthreads();
    int n = blockIdx.x * blockDim.x + tid;
    if (n < N_NODES) {
        int g = batch[n];
        atomicAdd(&ss[2 * g + 0], g_t3[2 * n + 0]);
        atomicAdd(&ss[2 * g + 1], g_t3[2 * n + 1]);
        atomicAdd(&sc[g], 1.0f);
    }
    __syncthreads();
    if (tid < N_GRAPHS * 2) atomicAdd(&g_gsum[tid], ss[tid]);
    if (tid < N_GRAPHS)     atomicAdd(&g_gcnt[tid], sc[tid]);
}

// K10: finalize out = gsum/cnt + b3
__global__ void k_final(const float* __restrict__ b3, float* __restrict__ out) {
    int i = threadIdx.x;
    if (i < N_GRAPHS * 2) {
        int g = i >> 1, j = i & 1;
        out[i] = g_gsum[i] / fmaxf(g_gcnt[g], 1.0f) + b3[j];
    }
}

// ---------------- launch ------------------------------------------------------
extern "C" void kernel_launch(void* const* d_in, const int* in_sizes, int n_in,
                              void* d_out, int out_size) {
    const float* x     = (const float*)d_in[0];
    const int*   ei    = (const int*)d_in[1];    // int32 (JAX x64 disabled)
    const int*   batch = (const int*)d_in[2];    // int32
    const float* W1    = (const float*)d_in[3];
    const float* b1    = (const float*)d_in[4];
    const float* W2    = (const float*)d_in[5];
    const float* b2    = (const float*)d_in[6];
    const float* W3    = (const float*)d_in[7];
    const float* b3    = (const float*)d_in[8];
    float* out = (float*)d_out;

    const int TB = 256;
    const int nb_nodes = (N_NODES + TB - 1) / TB;            // 391
    const int nb_edges = (N_EDGES + TB - 1) / TB;            // 12500
    const int nb_nwarp = (N_NODES * 32 + TB - 1) / TB;       // 12500
    const int nb_e8    = (N_EDGES * 8 + TB - 1) / TB;        // 100000

    k_init<<<nb_nodes, TB>>>();
    k_deg<<<nb_edges, TB>>>(ei);
    k_dinv_t1<<<nb_nodes, TB>>>(x);
    k_edge_l1<<<nb_edges, TB>>>(ei);
    k_node_l1<<<nb_nwarp, TB>>>(W1, b1);
    k_edge_l2<<<nb_e8, TB>>>(ei);
    k_node_l23<<<nb_nwarp, TB>>>(W2, b2, W3);
    k_edge_l3<<<nb_edges, TB>>>(ei);
    k_pool<<<nb_nodes, TB>>>(batch);
    k_final<<<1, 256>>>(b3, out);
}

// round 12
// speedup vs baseline: 1.2644x; 1.0865x over previous
#include <cuda_runtime.h>

#define N_NODES  100000
#define N_EDGES  3200000
#define N_GRAPHS 128
#define NB_SCAN  ((N_NODES + 255) / 256)   // 391

// ---------------- scratch (device globals) -----------------------------------
__device__ int   g_cnt[N_NODES];               // in-degree (no self-loop)
__device__ int   g_off[N_NODES + 1];           // CSR row offsets (by dst)
__device__ int   g_cur[N_NODES];               // scatter cursors
__device__ int   g_bsum[512];                  // block sums for scan
__device__ float g_dinv[N_NODES];
__device__ __align__(16)  float  g_y[N_NODES * 4];   // (dinv*x, dinv)
__device__ __align__(8)   float2 g_se[N_EDGES];      // (src_bits, dinv[src]) sorted by dst
__device__ __align__(128) float  g_h1[N_NODES * 32];
__device__ __align__(8)   float  g_p [N_NODES * 2];
__device__ __align__(8)   float  g_t3[N_NODES * 2];
__device__ float g_gsum[N_GRAPHS * 2];
__device__ float g_gcnt[N_GRAPHS];

// ---------------- kernels ----------------------------------------------------

__global__ void k_init() {
    int i = blockIdx.x * blockDim.x + threadIdx.x;
    if (i < N_NODES)      g_cnt[i] = 0;
    if (i < N_GRAPHS * 2) g_gsum[i] = 0.0f;
    if (i < N_GRAPHS)     g_gcnt[i] = 0.0f;
    if (i == 0)           g_off[N_NODES] = N_EDGES;
}

__global__ void k_hist(const int* __restrict__ ei) {
    int e = blockIdx.x * blockDim.x + threadIdx.x;
    if (e < N_EDGES) atomicAdd(&g_cnt[ei[N_EDGES + e]], 1);
}

__global__ void k_dinv(const float* __restrict__ x) {
    int i = blockIdx.x * blockDim.x + threadIdx.x;
    if (i >= N_NODES) return;
    float dv = rsqrtf((float)g_cnt[i] + 1.0f);   // +1 = self-loop
    g_dinv[i] = dv;
    *reinterpret_cast<float4*>(&g_y[4 * i]) =
        make_float4(dv * x[3 * i], dv * x[3 * i + 1], dv * x[3 * i + 2], dv);
}

// scan phase 1: per-block sums of g_cnt
__global__ void k_scan1() {
    __shared__ int sh[256];
    int tid = threadIdx.x;
    int i = blockIdx.x * 256 + tid;
    sh[tid] = (i < N_NODES) ? g_cnt[i] : 0;
    __syncthreads();
    for (int ofs = 128; ofs > 0; ofs >>= 1) {
        if (tid < ofs) sh[tid] += sh[tid + ofs];
        __syncthreads();
    }
    if (tid == 0) g_bsum[blockIdx.x] = sh[0];
}

// scan phase 2: exclusive scan of 391 block sums (1 block, 512 threads)
__global__ void k_scan2() {
    __shared__ int sh[512];
    int tid = threadIdx.x;
    int v = (tid < NB_SCAN) ? g_bsum[tid] : 0;
    sh[tid] = v;
    __syncthreads();
    for (int ofs = 1; ofs < 512; ofs <<= 1) {
        int t = (tid >= ofs) ? sh[tid - ofs] : 0;
        __syncthreads();
        sh[tid] += t;
        __syncthreads();
    }
    if (tid < NB_SCAN) g_bsum[tid] = sh[tid] - v;   // exclusive
}

// scan phase 3: per-block exclusive scan + block offset -> g_off, g_cur
__global__ void k_scan3() {
    __shared__ int sh[256];
    int tid = threadIdx.x;
    int i = blockIdx.x * 256 + tid;
    int v = (i < N_NODES) ? g_cnt[i] : 0;
    sh[tid] = v;
    __syncthreads();
    for (int ofs = 1; ofs < 256; ofs <<= 1) {
        int t = (tid >= ofs) ? sh[tid - ofs] : 0;
        __syncthreads();
        sh[tid] += t;
        __syncthreads();
    }
    if (i < N_NODES) {
        int off = g_bsum[blockIdx.x] + sh[tid] - v;
        g_off[i] = off;
        g_cur[i] = off;
    }
}

// scatter edges into dst-CSR, carrying (src, dinv[src])
__global__ void k_scatter(const int* __restrict__ ei) {
    int e = blockIdx.x * blockDim.x + threadIdx.x;
    if (e >= N_EDGES) return;
    int s = ei[e];
    int d = ei[N_EDGES + e];
    int pos = atomicAdd(&g_cur[d], 1);
    g_se[pos] = make_float2(__int_as_float(s), g_dinv[s]);
}

// L1 aggregation + 3->32 GEMV + ReLU, warp per dst node
__global__ void k_l1node1(const float* __restrict__ W1, const float* __restrict__ b1) {
    int gid = blockIdx.x * blockDim.x + threadIdx.x;
    int n = gid >> 5;
    int lane = gid & 31;
    if (n >= N_NODES) return;
    int o0 = g_off[n], o1 = g_off[n + 1];
    float ax = 0.0f, ay = 0.0f, az = 0.0f;
    for (int i = o0 + lane; i < o1; i += 32) {
        float2 se = g_se[i];
        int s = __float_as_int(se.x);
        const float4 ys = *reinterpret_cast<const float4*>(&g_y[4 * s]);
        ax += ys.x; ay += ys.y; az += ys.z;
    }
#pragma unroll
    for (int m = 16; m > 0; m >>= 1) {
        ax += __shfl_xor_sync(0xffffffffu, ax, m);
        ay += __shfl_xor_sync(0xffffffffu, ay, m);
        az += __shfl_xor_sync(0xffffffffu, az, m);
    }
    const float4 yn = *reinterpret_cast<const float4*>(&g_y[4 * n]);
    float dd = yn.w;
    float t1x = dd * (ax + yn.x);
    float t1y = dd * (ay + yn.y);
    float t1z = dd * (az + yn.z);
    float acc = b1[lane];
    acc = fmaf(t1x, W1[lane], acc);
    acc = fmaf(t1y, W1[32 + lane], acc);
    acc = fmaf(t1z, W1[64 + lane], acc);
    g_h1[(n << 5) + lane] = fmaxf(acc, 0.0f);
}

// L2 aggregation (warp pulls 128B h1 rows) + fused 32->64 ReLU + 64->2 GEMV
__global__ void k_l2node23(const float* __restrict__ W2, const float* __restrict__ b2,
                           const float* __restrict__ W3) {
    __shared__ float sW2[32 * 64];
    __shared__ float sW3[64 * 2];
    __shared__ float sb2[64];
    int tid = threadIdx.x;
    for (int i = tid; i < 32 * 64; i += blockDim.x) sW2[i] = W2[i];
    if (tid < 128) sW3[tid] = W3[tid];
    if (tid < 64)  sb2[tid] = b2[tid];
    __syncthreads();

    int lane = tid & 31;
    int gw = (blockIdx.x * blockDim.x + tid) >> 5;
    int nwarps = (gridDim.x * blockDim.x) >> 5;

    for (int n = gw; n < N_NODES; n += nwarps) {
        float dd = g_dinv[n];
        int o0 = g_off[n], o1 = g_off[n + 1];
        float acc = dd * dd * g_h1[(n << 5) + lane];   // self-loop term
        int i = o0;
        for (; i + 3 < o1; i += 4) {
            float2 e0 = g_se[i],     e1 = g_se[i + 1];
            float2 e2 = g_se[i + 2], e3 = g_se[i + 3];
            float v0 = g_h1[(__float_as_int(e0.x) << 5) + lane];
            float v1 = g_h1[(__float_as_int(e1.x) << 5) + lane];
            float v2 = g_h1[(__float_as_int(e2.x) << 5) + lane];
            float v3 = g_h1[(__float_as_int(e3.x) << 5) + lane];
            acc = fmaf(e0.y * dd, v0, acc);
            acc = fmaf(e1.y * dd, v1, acc);
            acc = fmaf(e2.y * dd, v2, acc);
            acc = fmaf(e3.y * dd, v3, acc);
        }
        for (; i < o1; i++) {
            float2 e0 = g_se[i];
            acc = fmaf(e0.y * dd, g_h1[(__float_as_int(e0.x) << 5) + lane], acc);
        }
        // t2 = acc (lane owns channel `lane`); GEMV 32->64, ReLU, 64->2
        float a0 = sb2[lane];
        float a1 = sb2[lane + 32];
#pragma unroll
        for (int k = 0; k < 32; k++) {
            float tk = __shfl_sync(0xffffffffu, acc, k);
            a0 = fmaf(tk, sW2[k * 64 + lane], a0);
            a1 = fmaf(tk, sW2[k * 64 + lane + 32], a1);
        }
        a0 = fmaxf(a0, 0.0f);
        a1 = fmaxf(a1, 0.0f);
        float c0 = a0 * sW3[2 * lane]     + a1 * sW3[2 * lane + 64];
        float c1 = a0 * sW3[2 * lane + 1] + a1 * sW3[2 * lane + 65];
#pragma unroll
        for (int m = 16; m > 0; m >>= 1) {
            c0 += __shfl_xor_sync(0xffffffffu, c0, m);
            c1 += __shfl_xor_sync(0xffffffffu, c1, m);
        }
        if (lane == 0)
            *reinterpret_cast<float2*>(&g_p[2 * n]) = make_float2(c0, c1);
    }
}

// L3 aggregation at width 2, warp per dst node
__global__ void k_l3() {
    int gid = blockIdx.x * blockDim.x + threadIdx.x;
    int n = gid >> 5;
    int lane = gid & 31;
    if (n >= N_NODES) return;
    int o0 = g_off[n], o1 = g_off[n + 1];
    float a0 = 0.0f, a1 = 0.0f;
    for (int i = o0 + lane; i < o1; i += 32) {
        float2 se = g_se[i];
        int s = __float_as_int(se.x);
        const float2 ps = *reinterpret_cast<const float2*>(&g_p[2 * s]);
        a0 = fmaf(se.y, ps.x, a0);
        a1 = fmaf(se.y, ps.y, a1);
    }
#pragma unroll
    for (int m = 16; m > 0; m >>= 1) {
        a0 += __shfl_xor_sync(0xffffffffu, a0, m);
        a1 += __shfl_xor_sync(0xffffffffu, a1, m);
    }
    if (lane == 0) {
        float dd = g_dinv[n];
        const float2 pn = *reinterpret_cast<const float2*>(&g_p[2 * n]);
        *reinterpret_cast<float2*>(&g_t3[2 * n]) =
            make_float2(dd * (a0 + dd * pn.x), dd * (a1 + dd * pn.y));
    }
}

// mean-pool: shared pre-reduction per block
__global__ void k_pool(const int* __restrict__ batch) {
    __shared__ float ss[N_GRAPHS * 2];
    __shared__ float sc[N_GRAPHS];
    int tid = threadIdx.x;
    for (int i = tid; i < N_GRAPHS * 2; i += blockDim.x) ss[i] = 0.0f;
    for (int i = tid; i < N_GRAPHS; i += blockDim.x)     sc[i] = 0.0f;
    __syncthreads();
    int n = blockIdx.x * blockDim.x + tid;
    if (n < N_NODES) {
        int g = batch[n];
        atomicAdd(&ss[2 * g + 0], g_t3[2 * n + 0]);
        atomicAdd(&ss[2 * g + 1], g_t3[2 * n + 1]);
        atomicAdd(&sc[g], 1.0f);
    }
    __syncthreads();
    if (tid < N_GRAPHS * 2) atomicAdd(&g_gsum[tid], ss[tid]);
    if (tid < N_GRAPHS)     atomicAdd(&g_gcnt[tid], sc[tid]);
}

__global__ void k_final(const float* __restrict__ b3, float* __restrict__ out) {
    int i = threadIdx.x;
    if (i < N_GRAPHS * 2) {
        int g = i >> 1, j = i & 1;
        out[i] = g_gsum[i] / fmaxf(g_gcnt[g], 1.0f) + b3[j];
    }
}

// ---------------- launch ------------------------------------------------------
extern "C" void kernel_launch(void* const* d_in, const int* in_sizes, int n_in,
                              void* d_out, int out_size) {
    const float* x     = (const float*)d_in[0];
    const int*   ei    = (const int*)d_in[1];    // int32 (JAX x64 disabled)
    const int*   batch = (const int*)d_in[2];
    const float* W1    = (const float*)d_in[3];
    const float* b1    = (const float*)d_in[4];
    const float* W2    = (const float*)d_in[5];
    const float* b2    = (const float*)d_in[6];
    const float* W3    = (const float*)d_in[7];
    const float* b3    = (const float*)d_in[8];
    float* out = (float*)d_out;

    const int TB = 256;
    const int nb_nodes = (N_NODES + TB - 1) / TB;        // 391
    const int nb_edges = (N_EDGES + TB - 1) / TB;        // 12500
    const int nb_nwarp = (N_NODES * 32 + TB - 1) / TB;   // 12500

    k_init<<<nb_nodes, TB>>>();
    k_hist<<<nb_edges, TB>>>(ei);
    k_dinv<<<nb_nodes, TB>>>(x);
    k_scan1<<<NB_SCAN, TB>>>();
    k_scan2<<<1, 512>>>();
    k_scan3<<<NB_SCAN, TB>>>();
    k_scatter<<<nb_edges, TB>>>(ei);
    k_l1node1<<<nb_nwarp, TB>>>(W1, b1);
    k_l2node23<<<2500, TB>>>(W2, b2, W3);
    k_l3<<<nb_nwarp, TB>>>();
    k_pool<<<nb_nodes, TB>>>(batch);
    k_final<<<1, 256>>>(b3, out);
}

// round 13
// speedup vs baseline: 1.2988x; 1.0272x over previous
#include <cuda_runtime.h>

#define N_NODES  100000
#define N_EDGES  3200000
#define N_GRAPHS 128
#define NB_SCAN  ((N_NODES + 255) / 256)   // 391

// ---------------- scratch (device globals) -----------------------------------
__device__ int   g_cnt[N_NODES];               // in-degree (zeroed by scan3 after use)
__device__ int   g_off[N_NODES + 1];           // CSR row offsets (by dst)
__device__ int   g_cur[N_NODES];               // scatter cursors
__device__ int   g_bsum[512];                  // block sums for scan
__device__ float g_dinv[N_NODES];
__device__ __align__(16)  float g_y[N_NODES * 4];    // (dinv*x0, dinv*x1, dinv*x2, dinv)
__device__ int   g_srcs[N_EDGES];                    // src ids sorted by dst
__device__ __align__(128) float g_h1[N_NODES * 32];  // dinv * relu(t1@W1+b1)
__device__ __align__(8)   float g_p [N_NODES * 2];   // dinv * ((relu(t2@W2+b2))@W3)
__device__ __align__(8)   float g_t3[N_NODES * 2];
__device__ float g_gsum[N_GRAPHS * 2];               // zeroed by k_final after use
__device__ float g_gcnt[N_GRAPHS];

// ---------------- kernels ----------------------------------------------------

__global__ void k_hist(const int* __restrict__ ei) {
    int e = blockIdx.x * blockDim.x + threadIdx.x;
    if (e < N_EDGES) atomicAdd(&g_cnt[ei[N_EDGES + e]], 1);
}

// scan phase 1: per-block sums of g_cnt
__global__ void k_scan1() {
    __shared__ int sh[256];
    int tid = threadIdx.x;
    int i = blockIdx.x * 256 + tid;
    sh[tid] = (i < N_NODES) ? g_cnt[i] : 0;
    __syncthreads();
    for (int ofs = 128; ofs > 0; ofs >>= 1) {
        if (tid < ofs) sh[tid] += sh[tid + ofs];
        __syncthreads();
    }
    if (tid == 0) g_bsum[blockIdx.x] = sh[0];
}

// scan phase 2: exclusive scan of 391 block sums (1 block, 512 threads)
__global__ void k_scan2() {
    __shared__ int sh[512];
    int tid = threadIdx.x;
    int v = (tid < NB_SCAN) ? g_bsum[tid] : 0;
    sh[tid] = v;
    __syncthreads();
    for (int ofs = 1; ofs < 512; ofs <<= 1) {
        int t = (tid >= ofs) ? sh[tid - ofs] : 0;
        __syncthreads();
        sh[tid] += t;
        __syncthreads();
    }
    if (tid < NB_SCAN) g_bsum[tid] = sh[tid] - v;   // exclusive
    if (tid == 0)      g_off[N_NODES] = N_EDGES;
}

// scan phase 3: per-block exclusive scan + block offset -> g_off, g_cur;
// fused: dinv = rsqrt(deg+1), y = (dinv*x, dinv); re-zero g_cnt for next replay
__global__ void k_scan3(const float* __restrict__ x) {
    __shared__ int sh[256];
    int tid = threadIdx.x;
    int i = blockIdx.x * 256 + tid;
    int v = (i < N_NODES) ? g_cnt[i] : 0;
    sh[tid] = v;
    __syncthreads();
    for (int ofs = 1; ofs < 256; ofs <<= 1) {
        int t = (tid >= ofs) ? sh[tid - ofs] : 0;
        __syncthreads();
        sh[tid] += t;
        __syncthreads();
    }
    if (i < N_NODES) {
        int off = g_bsum[blockIdx.x] + sh[tid] - v;
        g_off[i] = off;
        g_cur[i] = off;
        g_cnt[i] = 0;                                // ready for next replay
        float dv = rsqrtf((float)v + 1.0f);          // +1 = self-loop
        g_dinv[i] = dv;
        *reinterpret_cast<float4*>(&g_y[4 * i]) =
            make_float4(dv * x[3 * i], dv * x[3 * i + 1], dv * x[3 * i + 2], dv);
    }
}

// scatter edges into dst-CSR (src only — 4B payload)
__global__ void k_scatter(const int* __restrict__ ei) {
    int e = blockIdx.x * blockDim.x + threadIdx.x;
    if (e >= N_EDGES) return;
    int s = ei[e];
    int d = ei[N_EDGES + e];
    int pos = atomicAdd(&g_cur[d], 1);
    g_srcs[pos] = s;
}

// L1 aggregation + 3->32 GEMV + ReLU, warp per dst node; writes h1' = dinv*relu
__global__ void k_l1node1(const float* __restrict__ W1, const float* __restrict__ b1) {
    int gid = blockIdx.x * blockDim.x + threadIdx.x;
    int n = gid >> 5;
    int lane = gid & 31;
    if (n >= N_NODES) return;
    int o0 = g_off[n], o1 = g_off[n + 1];
    float ax = 0.0f, ay = 0.0f, az = 0.0f;
    for (int i = o0 + lane; i < o1; i += 32) {
        const float4 ys = *reinterpret_cast<const float4*>(&g_y[4 * g_srcs[i]]);
        ax += ys.x; ay += ys.y; az += ys.z;
    }
#pragma unroll
    for (int m = 16; m > 0; m >>= 1) {
        ax += __shfl_xor_sync(0xffffffffu, ax, m);
        ay += __shfl_xor_sync(0xffffffffu, ay, m);
        az += __shfl_xor_sync(0xffffffffu, az, m);
    }
    const float4 yn = *reinterpret_cast<const float4*>(&g_y[4 * n]);
    float dd = yn.w;
    float t1x = dd * (ax + yn.x);
    float t1y = dd * (ay + yn.y);
    float t1z = dd * (az + yn.z);
    float acc = b1[lane];
    acc = fmaf(t1x, W1[lane], acc);
    acc = fmaf(t1y, W1[32 + lane], acc);
    acc = fmaf(t1z, W1[64 + lane], acc);
    g_h1[(n << 5) + lane] = dd * fmaxf(acc, 0.0f);   // pre-scaled h1'
}

// L2 aggregation (coalesced src list + shfl-distribute, 128B row pulls)
// + fused 32->64 ReLU + 64->2 GEMV; writes p' = dinv*p
__global__ void k_l2node23(const float* __restrict__ W2, const float* __restrict__ b2,
                           const float* __restrict__ W3) {
    __shared__ float sW2[32 * 64];
    __shared__ float sW3[64 * 2];
    __shared__ float sb2[64];
    int tid = threadIdx.x;
    for (int i = tid; i < 32 * 64; i += blockDim.x) sW2[i] = W2[i];
    if (tid < 128) sW3[tid] = W3[tid];
    if (tid < 64)  sb2[tid] = b2[tid];
    __syncthreads();

    int lane = tid & 31;
    int gw = (blockIdx.x * blockDim.x + tid) >> 5;
    int nwarps = (gridDim.x * blockDim.x) >> 5;

    for (int n = gw; n < N_NODES; n += nwarps) {
        float dd = g_dinv[n];
        int o0 = g_off[n], o1 = g_off[n + 1];
        float acc = g_h1[(n << 5) + lane];           // self term (h1' already scaled)
        int i = o0;
        for (; i + 32 <= o1; i += 32) {
            int s = g_srcs[i + lane];                // one coalesced 128B load
#pragma unroll
            for (int j = 0; j < 32; j++) {
                int sj = __shfl_sync(0xffffffffu, s, j);
                acc += g_h1[(sj << 5) + lane];       // 32 independent row pulls
            }
        }
        int rem = o1 - i;
        if (rem > 0) {
            int s = (lane < rem) ? g_srcs[i + lane] : 0;
            for (int j = 0; j < rem; j++) {
                int sj = __shfl_sync(0xffffffffu, s, j);
                acc += g_h1[(sj << 5) + lane];
            }
        }
        float t2 = dd * acc;
        // GEMV 32->64 + ReLU + 64->2
        float a0 = sb2[lane];
        float a1 = sb2[lane + 32];
#pragma unroll
        for (int k = 0; k < 32; k++) {
            float tk = __shfl_sync(0xffffffffu, t2, k);
            a0 = fmaf(tk, sW2[k * 64 + lane], a0);
            a1 = fmaf(tk, sW2[k * 64 + lane + 32], a1);
        }
        a0 = fmaxf(a0, 0.0f);
        a1 = fmaxf(a1, 0.0f);
        float c0 = a0 * sW3[2 * lane]     + a1 * sW3[2 * lane + 64];
        float c1 = a0 * sW3[2 * lane + 1] + a1 * sW3[2 * lane + 65];
#pragma unroll
        for (int m = 16; m > 0; m >>= 1) {
            c0 += __shfl_xor_sync(0xffffffffu, c0, m);
            c1 += __shfl_xor_sync(0xffffffffu, c1, m);
        }
        if (lane == 0)
            *reinterpret_cast<float2*>(&g_p[2 * n]) = make_float2(dd * c0, dd * c1);
    }
}

// L3 aggregation at width 2, warp per dst node (p' pre-scaled)
__global__ void k_l3() {
    int gid = blockIdx.x * blockDim.x + threadIdx.x;
    int n = gid >> 5;
    int lane = gid & 31;
    if (n >= N_NODES) return;
    int o0 = g_off[n], o1 = g_off[n + 1];
    float a0 = 0.0f, a1 = 0.0f;
    for (int i = o0 + lane; i < o1; i += 32) {
        const float2 ps = *reinterpret_cast<const float2*>(&g_p[2 * g_srcs[i]]);
        a0 += ps.x;
        a1 += ps.y;
    }
#pragma unroll
    for (int m = 16; m > 0; m >>= 1) {
        a0 += __shfl_xor_sync(0xffffffffu, a0, m);
        a1 += __shfl_xor_sync(0xffffffffu, a1, m);
    }
    if (lane == 0) {
        float dd = g_dinv[n];
        const float2 pn = *reinterpret_cast<const float2*>(&g_p[2 * n]);
        *reinterpret_cast<float2*>(&g_t3[2 * n]) =
            make_float2(dd * (a0 + pn.x), dd * (a1 + pn.y));
    }
}

// mean-pool: shared pre-reduction per block
__global__ void k_pool(const int* __restrict__ batch) {
    __shared__ float ss[N_GRAPHS * 2];
    __shared__ float sc[N_GRAPHS];
    int tid = threadIdx.x;
    for (int i = tid; i < N_GRAPHS * 2; i += blockDim.x) ss[i] = 0.0f;
    for (int i = tid; i < N_GRAPHS; i += blockDim.x)     sc[i] = 0.0f;
    __syncthreads();
    int n = blockIdx.x * blockDim.x + tid;
    if (n < N_NODES) {
        int g = batch[n];
        atomicAdd(&ss[2 * g + 0], g_t3[2 * n + 0]);
        atomicAdd(&ss[2 * g + 1], g_t3[2 * n + 1]);
        atomicAdd(&sc[g], 1.0f);
    }
    __syncthreads();
    if (tid < N_GRAPHS * 2) atomicAdd(&g_gsum[tid], ss[tid]);
    if (tid < N_GRAPHS)     atomicAdd(&g_gcnt[tid], sc[tid]);
}

// finalize + reset pool accumulators for next replay
__global__ void k_final(const float* __restrict__ b3, float* __restrict__ out) {
    int i = threadIdx.x;
    float r = 0.0f;
    if (i < N_GRAPHS * 2) {
        int g = i >> 1, j = i & 1;
        r = g_gsum[i] / fmaxf(g_gcnt[g], 1.0f) + b3[j];
    }
    __syncthreads();
    if (i < N_GRAPHS * 2) {
        out[i] = r;
        g_gsum[i] = 0.0f;
    }
    if (i < N_GRAPHS) g_gcnt[i] = 0.0f;
}

// ---------------- launch ------------------------------------------------------
extern "C" void kernel_launch(void* const* d_in, const int* in_sizes, int n_in,
                              void* d_out, int out_size) {
    const float* x     = (const float*)d_in[0];
    const int*   ei    = (const int*)d_in[1];    // int32 (JAX x64 disabled)
    const int*   batch = (const int*)d_in[2];
    const float* W1    = (const float*)d_in[3];
    const float* b1    = (const float*)d_in[4];
    const float* W2    = (const float*)d_in[5];
    const float* b2    = (const float*)d_in[6];
    const float* W3    = (const float*)d_in[7];
    const float* b3    = (const float*)d_in[8];
    float* out = (float*)d_out;

    const int TB = 256;
    const int nb_nodes = (N_NODES + TB - 1) / TB;        // 391
    const int nb_edges = (N_EDGES + TB - 1) / TB;        // 12500
    const int nb_nwarp = (N_NODES * 32 + TB - 1) / TB;   // 12500

    k_hist<<<nb_edges, TB>>>(ei);
    k_scan1<<<NB_SCAN, TB>>>();
    k_scan2<<<1, 512>>>();
    k_scan3<<<NB_SCAN, TB>>>(x);
    k_scatter<<<nb_edges, TB>>>(ei);
    k_l1node1<<<nb_nwarp, TB>>>(W1, b1);
    k_l2node23<<<2500, TB>>>(W2, b2, W3);
    k_l3<<<nb_nwarp, TB>>>();
    k_pool<<<nb_nodes, TB>>>(batch);
    k_final<<<1, 256>>>(b3, out);
}

// round 14
// speedup vs baseline: 1.3461x; 1.0364x over previous
#include <cuda_runtime.h>
#include <cuda_fp16.h>

#define N_NODES  100000
#define N_EDGES  3200000
#define N_GRAPHS 128
#define NB_SCAN  ((N_NODES + 255) / 256)   // 391

// ---------------- scratch (device globals) -----------------------------------
__device__ int   g_cnt[N_NODES];               // in-degree (zeroed by scan3 after use)
__device__ int   g_off[N_NODES + 1];           // CSR row offsets (by dst)
__device__ int   g_cur[N_NODES];               // scatter cursors
__device__ int   g_bsum[512];                  // block sums for scan
__device__ float g_dinv[N_NODES];
__device__ __align__(16) float g_y[N_NODES * 4];     // (dinv*x0, dinv*x1, dinv*x2, dinv)
__device__ int   g_srcs[N_EDGES];                    // src ids sorted by dst
__device__ __align__(64) __half g_h1[N_NODES * 32];  // fp16: dinv * relu(t1@W1+b1)
__device__ __align__(8)  float  g_p [N_NODES * 2];   // dinv * ((relu(t2@W2+b2))@W3)
__device__ __align__(8)  float  g_t3[N_NODES * 2];
__device__ float g_gsum[N_GRAPHS * 2];               // zeroed by k_final after use
__device__ float g_gcnt[N_GRAPHS];

// ---------------- kernels ----------------------------------------------------

__global__ void k_hist(const int* __restrict__ ei) {
    int e = blockIdx.x * blockDim.x + threadIdx.x;
    if (e < N_EDGES) atomicAdd(&g_cnt[ei[N_EDGES + e]], 1);
}

// scan phase 1: per-block sums of g_cnt
__global__ void k_scan1() {
    __shared__ int sh[256];
    int tid = threadIdx.x;
    int i = blockIdx.x * 256 + tid;
    sh[tid] = (i < N_NODES) ? g_cnt[i] : 0;
    __syncthreads();
    for (int ofs = 128; ofs > 0; ofs >>= 1) {
        if (tid < ofs) sh[tid] += sh[tid + ofs];
        __syncthreads();
    }
    if (tid == 0) g_bsum[blockIdx.x] = sh[0];
}

// scan phase 2: exclusive scan of 391 block sums (1 block, 512 threads)
__global__ void k_scan2() {
    __shared__ int sh[512];
    int tid = threadIdx.x;
    int v = (tid < NB_SCAN) ? g_bsum[tid] : 0;
    sh[tid] = v;
    __syncthreads();
    for (int ofs = 1; ofs < 512; ofs <<= 1) {
        int t = (tid >= ofs) ? sh[tid - ofs] : 0;
        __syncthreads();
        sh[tid] += t;
        __syncthreads();
    }
    if (tid < NB_SCAN) g_bsum[tid] = sh[tid] - v;   // exclusive
    if (tid == 0)      g_off[N_NODES] = N_EDGES;
}

// scan phase 3: per-block exclusive scan + block offset -> g_off, g_cur;
// fused: dinv = rsqrt(deg+1), y = (dinv*x, dinv); re-zero g_cnt for next replay
__global__ void k_scan3(const float* __restrict__ x) {
    __shared__ int sh[256];
    int tid = threadIdx.x;
    int i = blockIdx.x * 256 + tid;
    int v = (i < N_NODES) ? g_cnt[i] : 0;
    sh[tid] = v;
    __syncthreads();
    for (int ofs = 1; ofs < 256; ofs <<= 1) {
        int t = (tid >= ofs) ? sh[tid - ofs] : 0;
        __syncthreads();
        sh[tid] += t;
        __syncthreads();
    }
    if (i < N_NODES) {
        int off = g_bsum[blockIdx.x] + sh[tid] - v;
        g_off[i] = off;
        g_cur[i] = off;
        g_cnt[i] = 0;                                // ready for next replay
        float dv = rsqrtf((float)v + 1.0f);          // +1 = self-loop
        g_dinv[i] = dv;
        *reinterpret_cast<float4*>(&g_y[4 * i]) =
            make_float4(dv * x[3 * i], dv * x[3 * i + 1], dv * x[3 * i + 2], dv);
    }
}

// scatter edges into dst-CSR (src only — 4B payload)
__global__ void k_scatter(const int* __restrict__ ei) {
    int e = blockIdx.x * blockDim.x + threadIdx.x;
    if (e >= N_EDGES) return;
    int s = ei[e];
    int d = ei[N_EDGES + e];
    int pos = atomicAdd(&g_cur[d], 1);
    g_srcs[pos] = s;
}

// L1 aggregation + 3->32 GEMV + ReLU, warp per dst node; writes h1' = fp16(dinv*relu)
__global__ void k_l1node1(const float* __restrict__ W1, const float* __restrict__ b1) {
    int gid = blockIdx.x * blockDim.x + threadIdx.x;
    int n = gid >> 5;
    int lane = gid & 31;
    if (n >= N_NODES) return;
    int o0 = g_off[n], o1 = g_off[n + 1];
    float ax = 0.0f, ay = 0.0f, az = 0.0f;
    for (int i = o0 + lane; i < o1; i += 32) {
        const float4 ys = *reinterpret_cast<const float4*>(&g_y[4 * g_srcs[i]]);
        ax += ys.x; ay += ys.y; az += ys.z;
    }
#pragma unroll
    for (int m = 16; m > 0; m >>= 1) {
        ax += __shfl_xor_sync(0xffffffffu, ax, m);
        ay += __shfl_xor_sync(0xffffffffu, ay, m);
        az += __shfl_xor_sync(0xffffffffu, az, m);
    }
    const float4 yn = *reinterpret_cast<const float4*>(&g_y[4 * n]);
    float dd = yn.w;
    float t1x = dd * (ax + yn.x);
    float t1y = dd * (ay + yn.y);
    float t1z = dd * (az + yn.z);
    float acc = b1[lane];
    acc = fmaf(t1x, W1[lane], acc);
    acc = fmaf(t1y, W1[32 + lane], acc);
    acc = fmaf(t1z, W1[64 + lane], acc);
    g_h1[(n << 5) + lane] = __float2half(dd * fmaxf(acc, 0.0f));   // pre-scaled h1'
}

// L2 aggregation (coalesced src list + shfl-distribute, 64B fp16 row pulls)
// + fused 32->64 ReLU + 64->2 GEMV; writes p' = dinv*p
__global__ void k_l2node23(const float* __restrict__ W2, const float* __restrict__ b2,
                           const float* __restrict__ W3) {
    __shared__ float sW2[32 * 64];
    __shared__ float sW3[64 * 2];
    __shared__ float sb2[64];
    int tid = threadIdx.x;
    for (int i = tid; i < 32 * 64; i += blockDim.x) sW2[i] = W2[i];
    if (tid < 128) sW3[tid] = W3[tid];
    if (tid < 64)  sb2[tid] = b2[tid];
    __syncthreads();

    int lane = tid & 31;
    int gw = (blockIdx.x * blockDim.x + tid) >> 5;
    int nwarps = (gridDim.x * blockDim.x) >> 5;

    for (int n = gw; n < N_NODES; n += nwarps) {
        float dd = g_dinv[n];
        int o0 = g_off[n], o1 = g_off[n + 1];
        float acc = __half2float(g_h1[(n << 5) + lane]);   // self term (pre-scaled)
        int i = o0;
        for (; i + 32 <= o1; i += 32) {
            int s = g_srcs[i + lane];                // one coalesced 128B load
#pragma unroll
            for (int j = 0; j < 32; j++) {
                int sj = __shfl_sync(0xffffffffu, s, j);
                acc += __half2float(g_h1[(sj << 5) + lane]);  // 64B row pulls
            }
        }
        int rem = o1 - i;
        if (rem > 0) {
            int s = (lane < rem) ? g_srcs[i + lane] : 0;
            for (int j = 0; j < rem; j++) {
                int sj = __shfl_sync(0xffffffffu, s, j);
                acc += __half2float(g_h1[(sj << 5) + lane]);
            }
        }
        float t2 = dd * acc;
        // GEMV 32->64 + ReLU + 64->2
        float a0 = sb2[lane];
        float a1 = sb2[lane + 32];
#pragma unroll
        for (int k = 0; k < 32; k++) {
            float tk = __shfl_sync(0xffffffffu, t2, k);
            a0 = fmaf(tk, sW2[k * 64 + lane], a0);
            a1 = fmaf(tk, sW2[k * 64 + lane + 32], a1);
        }
        a0 = fmaxf(a0, 0.0f);
        a1 = fmaxf(a1, 0.0f);
        float c0 = a0 * sW3[2 * lane]     + a1 * sW3[2 * lane + 64];
        float c1 = a0 * sW3[2 * lane + 1] + a1 * sW3[2 * lane + 65];
#pragma unroll
        for (int m = 16; m > 0; m >>= 1) {
            c0 += __shfl_xor_sync(0xffffffffu, c0, m);
            c1 += __shfl_xor_sync(0xffffffffu, c1, m);
        }
        if (lane == 0)
            *reinterpret_cast<float2*>(&g_p[2 * n]) = make_float2(dd * c0, dd * c1);
    }
}

// L3 aggregation at width 2, warp per dst node (p' pre-scaled)
__global__ void k_l3() {
    int gid = blockIdx.x * blockDim.x + threadIdx.x;
    int n = gid >> 5;
    int lane = gid & 31;
    if (n >= N_NODES) return;
    int o0 = g_off[n], o1 = g_off[n + 1];
    float a0 = 0.0f, a1 = 0.0f;
    for (int i = o0 + lane; i < o1; i += 32) {
        const float2 ps = *reinterpret_cast<const float2*>(&g_p[2 * g_srcs[i]]);
        a0 += ps.x;
        a1 += ps.y;
    }
#pragma unroll
    for (int m = 16; m > 0; m >>= 1) {
        a0 += __shfl_xor_sync(0xffffffffu, a0, m);
        a1 += __shfl_xor_sync(0xffffffffu, a1, m);
    }
    if (lane == 0) {
        float dd = g_dinv[n];
        const float2 pn = *reinterpret_cast<const float2*>(&g_p[2 * n]);
        *reinterpret_cast<float2*>(&g_t3[2 * n]) =
            make_float2(dd * (a0 + pn.x), dd * (a1 + pn.y));
    }
}

// mean-pool: shared pre-reduction per block
__global__ void k_pool(const int* __restrict__ batch) {
    __shared__ float ss[N_GRAPHS * 2];
    __shared__ float sc[N_GRAPHS];
    int tid = threadIdx.x;
    for (int i = tid; i < N_GRAPHS * 2; i += blockDim.x) ss[i] = 0.0f;
    for (int i = tid; i < N_GRAPHS; i += blockDim.x)     sc[i] = 0.0f;
    __syncthreads();
    int n = blockIdx.x * blockDim.x + tid;
    if (n < N_NODES) {
        int g = batch[n];
        atomicAdd(&ss[2 * g + 0], g_t3[2 * n + 0]);
        atomicAdd(&ss[2 * g + 1], g_t3[2 * n + 1]);
        atomicAdd(&sc[g], 1.0f);
    }
    __syncthreads();
    if (tid < N_GRAPHS * 2) atomicAdd(&g_gsum[tid], ss[tid]);
    if (tid < N_GRAPHS)     atomicAdd(&g_gcnt[tid], sc[tid]);
}

// finalize + reset pool accumulators for next replay
__global__ void k_final(const float* __restrict__ b3, float* __restrict__ out) {
    int i = threadIdx.x;
    float r = 0.0f;
    if (i < N_GRAPHS * 2) {
        int g = i >> 1, j = i & 1;
        r = g_gsum[i] / fmaxf(g_gcnt[g], 1.0f) + b3[j];
    }
    __syncthreads();
    if (i < N_GRAPHS * 2) {
        out[i] = r;
        g_gsum[i] = 0.0f;
    }
    if (i < N_GRAPHS) g_gcnt[i] = 0.0f;
}

// ---------------- launch ------------------------------------------------------
extern "C" void kernel_launch(void* const* d_in, const int* in_sizes, int n_in,
                              void* d_out, int out_size) {
    const float* x     = (const float*)d_in[0];
    const int*   ei    = (const int*)d_in[1];    // int32 (JAX x64 disabled)
    const int*   batch = (const int*)d_in[2];
    const float* W1    = (const float*)d_in[3];
    const float* b1    = (const float*)d_in[4];
    const float* W2    = (const float*)d_in[5];
    const float* b2    = (const float*)d_in[6];
    const float* W3    = (const float*)d_in[7];
    const float* b3    = (const float*)d_in[8];
    float* out = (float*)d_out;

    const int TB = 256;
    const int nb_nodes = (N_NODES + TB - 1) / TB;        // 391
    const int nb_edges = (N_EDGES + TB - 1) / TB;        // 12500
    const int nb_nwarp = (N_NODES * 32 + TB - 1) / TB;   // 12500

    k_hist<<<nb_edges, TB>>>(ei);
    k_scan1<<<NB_SCAN, TB>>>();
    k_scan2<<<1, 512>>>();
    k_scan3<<<NB_SCAN, TB>>>(x);
    k_scatter<<<nb_edges, TB>>>(ei);
    k_l1node1<<<nb_nwarp, TB>>>(W1, b1);
    k_l2node23<<<1184, TB>>>(W2, b2, W3);   // 8 blocks/SM, grid-stride
    k_l3<<<nb_nwarp, TB>>>();
    k_pool<<<nb_nodes, TB>>>(batch);
    k_final<<<1, 256>>>(b3, out);
}